// round 13
// baseline (speedup 1.0000x reference)
#include <cuda_runtime.h>
#include <math.h>
#include <mma.h>
using namespace nvcuda;

#define BN 4
#define IH 512
#define IW 512
#define TT 52
#define HALO 6
#define PAD2 32
#define A2 2112
#define TV_SMEM (2*A2*8)

// ---------------- static scratch ----------------
__device__ float g_pA[BN*2*IH*IW];
__device__ float g_pB[BN*2*IH*IW];
__device__ float g_den[BN*IH*IW];
__device__ float g_bufA[8*1024*1024];
__device__ float g_bufB[4*1024*1024];
__device__ float g_spart[8*BN*256];

__device__ __forceinline__ float silu(float x){ return x/(1.f+__expf(-x)); }

// ---- TV Chambolle: 5 fused iterations, float2, x-neighbors via warp shuffle ----
template<bool FIRST, bool INTERIOR, bool WRITE_P, bool WRITE_DEN>
__device__ __forceinline__ void tv_body(
    const float* __restrict__ img, const float* __restrict__ pin,
    float* __restrict__ pout, float* __restrict__ den,
    float2* s0, float2* so)
{
    const int b   = blockIdx.z;
    const int gy0 = blockIdx.y*TT - HALO;
    const int gx0 = blockIdx.x*TT - HALO;
    const int tid = threadIdx.x;
    const int lx2 = tid & 31;          // float2 column == lane
    const int ty0 = tid >> 5;
    const int gxp = gx0 + 2*lx2;
    const float* ib = img + b*(IH*IW);
    const float* q0 = pin + (b*2+0)*(IH*IW);
    const float* q1 = pin + (b*2+1)*(IH*IW);
    const unsigned FM = 0xffffffffu;

    float2 imgv[8], p0v[8], p1v[8];

#pragma unroll
    for(int k=0;k<8;k++){
        const int ly = ty0 + 8*k;
        const int gy = gy0 + ly;
        const int i  = k*256 + tid;
        if(INTERIOR){
            const int g2 = gy*(IW/2) + (gxp>>1);
            imgv[k] = ((const float2*)ib)[g2];
            if(FIRST){ p0v[k]=make_float2(0.f,0.f); p1v[k]=make_float2(0.f,0.f); }
            else { p0v[k]=((const float2*)q0)[g2]; p1v[k]=((const float2*)q1)[g2]; }
        } else {
            const bool iy  = ((unsigned)gy < IH);
            const bool inx = iy && ((unsigned)gxp < IW);
            const bool iny = iy && ((unsigned)(gxp+1) < IW);
            const int gA = gy*IW + gxp, gB = gA+1;
            imgv[k].x = inx ? ib[gA] : 0.f;
            imgv[k].y = iny ? ib[gB] : 0.f;
            if(FIRST){ p0v[k]=make_float2(0.f,0.f); p1v[k]=make_float2(0.f,0.f); }
            else{
                p0v[k].x = inx? q0[gA]:0.f; p0v[k].y = iny? q0[gB]:0.f;
                p1v[k].x = inx? q1[gA]:0.f; p1v[k].y = iny? q1[gB]:0.f;
            }
        }
        s0[i]=p0v[k];
    }
    __syncthreads();

#pragma unroll 1
    for(int it=0; it<5; it++){
        // pass1: out = img + div(p); left-p1 via shuffle, up-p0 via smem
#pragma unroll
        for(int k=0;k<8;k++){
            const int i = k*256 + tid;
            float2 up = s0[i-32];
            float  lf = __shfl_up_sync(FM, p1v[k].y, 1);   // lane0 garbage -> halo
            float2 o;
            o.x = imgv[k].x - p0v[k].x - p1v[k].x + up.x + lf;
            o.y = imgv[k].y - p0v[k].y - p1v[k].y + up.y + p1v[k].x;
            so[i] = o;
        }
        __syncthreads();
        // pass2: p update; right-out via shuffle, down-out via smem
#pragma unroll
        for(int k=0;k<8;k++){
            const int i  = k*256 + tid;
            const int gy = gy0 + ty0 + 8*k;
            float2 o  = so[i];
            float2 dn = so[i+32];
            float  rx = __shfl_down_sync(FM, o.x, 1);      // lane31 garbage -> halo
            float gyx = dn.x - o.x, gyy = dn.y - o.y;
            float gxx = o.y  - o.x, gxy = rx   - o.y;
            if(!INTERIOR){
                if(gy >= IH-1){ gyx=0.f; gyy=0.f; }
                if(gxp+1 >= IW-1) gxy = 0.f;
            }
            float n2x = fmaf(gyx,gyx, gxx*gxx);
            float n2y = fmaf(gyy,gyy, gxy*gxy);
            float nrx, nry, ivx, ivy;
            asm("sqrt.approx.f32 %0, %1;" : "=f"(nrx) : "f"(n2x));
            asm("sqrt.approx.f32 %0, %1;" : "=f"(nry) : "f"(n2y));
            float dx_ = fmaf(2.5f, nrx, 1.0f);
            float dy_ = fmaf(2.5f, nry, 1.0f);
            asm("rcp.approx.f32 %0, %1;" : "=f"(ivx) : "f"(dx_));
            asm("rcp.approx.f32 %0, %1;" : "=f"(ivy) : "f"(dy_));
            float2 np0, np1;
            np0.x = (p0v[k].x - 0.25f*gyx)*ivx;
            np1.x = (p1v[k].x - 0.25f*gxx)*ivx;
            np0.y = (p0v[k].y - 0.25f*gyy)*ivy;
            np1.y = (p1v[k].y - 0.25f*gxy)*ivy;
            if(!INTERIOR){
                const bool iy  = ((unsigned)gy < IH);
                const bool inx = iy && ((unsigned)gxp < IW);
                const bool iny = iy && ((unsigned)(gxp+1) < IW);
                if(!inx){ np0.x=0.f; np1.x=0.f; }
                if(!iny){ np0.y=0.f; np1.y=0.f; }
            }
            p0v[k]=np0; p1v[k]=np1;
            s0[i]=np0;
        }
        __syncthreads();
    }

    const bool wx = (lx2>=3) && (lx2<29) && (gxp < IW);
    if(WRITE_P){
        float2* o0 = (float2*)(pout + (b*2+0)*(IH*IW));
        float2* o1 = (float2*)(pout + (b*2+1)*(IH*IW));
#pragma unroll
        for(int k=0;k<8;k++){
            const int ly = ty0+8*k, gy = gy0+ly;
            if(wx && ly>=HALO && ly<HALO+TT && gy<IH){
                const int g2 = gy*(IW/2) + (gxp>>1);
                o0[g2]=p0v[k]; o1[g2]=p1v[k];
            }
        }
    }
    if(WRITE_DEN){
        float2* db = (float2*)(den + b*(IH*IW));
#pragma unroll
        for(int k=0;k<8;k++){
            const int ly = ty0+8*k, gy = gy0+ly;
            const int i  = k*256+tid;
            float2 up = s0[i-32];
            float  lf = __shfl_up_sync(FM, p1v[k].y, 1);   // warp-uniform
            if(wx && ly>=HALO && ly<HALO+TT && gy<IH){
                float2 d;
                d.x = imgv[k].x - p0v[k].x - p1v[k].x + up.x + lf;
                d.y = imgv[k].y - p0v[k].y - p1v[k].y + up.y + p1v[k].x;
                db[gy*(IW/2) + (gxp>>1)] = d;
            }
        }
    }
}

template<bool FIRST, bool WRITE_P, bool WRITE_DEN>
__global__ __launch_bounds__(256,3)
void tv5_k(const float* __restrict__ img, const float* __restrict__ pin,
           float* __restrict__ pout, float* __restrict__ den){
    extern __shared__ float2 sm2[];
    float2* s0 = sm2 + PAD2;
    float2* so = sm2 + A2 + PAD2;
    const bool interior = (blockIdx.y>=1 && blockIdx.y<=8 &&
                           blockIdx.x>=1 && blockIdx.x<=8);
    if(interior) tv_body<FIRST,true ,WRITE_P,WRITE_DEN>(img,pin,pout,den,s0,so);
    else         tv_body<FIRST,false,WRITE_P,WRITE_DEN>(img,pin,pout,den,s0,so);
}

// ---------------- stem: 1->32ch 3x3 stride2 + silu (fp32) ----------------
__global__ void stem_k(const float* __restrict__ x, const float* __restrict__ w,
                       float* __restrict__ y){
    __shared__ float sw[288];
    for(int i=threadIdx.x;i<288;i+=256) sw[i]=w[i];
    __syncthreads();
    int idx = blockIdx.x*256 + threadIdx.x;
    int b = idx>>16; int r = idx & 65535; int oy=r>>8, ox=r&255;
    const float* xb = x + b*IH*IW;
    float patch[9];
#pragma unroll
    for(int ky=0;ky<3;ky++)
#pragma unroll
    for(int kx=0;kx<3;kx++){
        int iy=2*oy-1+ky, ix=2*ox-1+kx;
        patch[ky*3+kx] = (iy>=0&&iy<IH&&ix>=0&&ix<IW)? xb[iy*IW+ix] : 0.f;
    }
    float* yb = y + (size_t)(b*32)*65536 + oy*256 + ox;
#pragma unroll
    for(int c=0;c<32;c++){
        float acc=0.f;
#pragma unroll
        for(int k=0;k<9;k++) acc += patch[k]*sw[c*9+k];
        yb[c*65536] = silu(acc);
    }
}

// ---------------- depthwise 3x3 stride2 + silu ----------------
__global__ void dw_k(const float* __restrict__ x, const float* __restrict__ w,
                     float* __restrict__ y, int C, int Hi, int Ho){
    int idx = blockIdx.x*256 + threadIdx.x;
    if(idx >= BN*C*Ho*Ho) return;
    int ox = idx % Ho; int t = idx/Ho; int oy=t%Ho; t/=Ho; int c=t%C; int b=t/C;
    const float* xb = x + (size_t)(b*C+c)*Hi*Hi;
    const float* wc = w + c*9;
    float acc=0.f;
#pragma unroll
    for(int ky=0;ky<3;ky++){
        int iy=2*oy-1+ky; if(iy<0||iy>=Hi) continue;
#pragma unroll
        for(int kx=0;kx<3;kx++){
            int ix=2*ox-1+kx; if(ix<0||ix>=Hi) continue;
            acc += xb[iy*Hi+ix]*wc[ky*3+kx];
        }
    }
    y[idx] = silu(acc);
}

// ---------------- big pointwise GEMM: BM=64, BN=128, 128 thr, 8x8 micro ----------------
__global__ __launch_bounds__(128)
void pwb_k(const float* __restrict__ x, const float* __restrict__ w,
           float* __restrict__ y, int M, int K, int HW){
    const int b = blockIdx.z, m0 = blockIdx.y*64, p0 = blockIdx.x*128;
    __shared__ float As[16][68];
    __shared__ float Bs[16][128];
    const int tid = threadIdx.x;
    const int tr = tid>>4, tc = tid&15;
    float acc[8][8] = {};
    const float* xb = x + (size_t)b*K*HW;
    for(int k0=0;k0<K;k0+=16){
#pragma unroll
        for(int r=0;r<2;r++){
            int m = (tid>>2) + 32*r;
            int q = (tid&3)*4;
            float4 v = *(const float4*)&w[(size_t)(m0+m)*K + k0 + q];
            As[q+0][m]=v.x; As[q+1][m]=v.y; As[q+2][m]=v.z; As[q+3][m]=v.w;
        }
#pragma unroll
        for(int r=0;r<4;r++){
            int kk = (tid>>5) + 4*r;
            int p  = (tid&31)*4;
            *(float4*)&Bs[kk][p] = *(const float4*)&xb[(size_t)(k0+kk)*HW + p0 + p];
        }
        __syncthreads();
#pragma unroll
        for(int kk=0;kk<16;kk++){
            float a[8], bv[8];
            *(float4*)&a[0]  = *(float4*)&As[kk][tr*8];
            *(float4*)&a[4]  = *(float4*)&As[kk][tr*8+4];
            *(float4*)&bv[0] = *(float4*)&Bs[kk][tc*8];
            *(float4*)&bv[4] = *(float4*)&Bs[kk][tc*8+4];
#pragma unroll
            for(int i=0;i<8;i++)
#pragma unroll
            for(int j=0;j<8;j++)
                acc[i][j] = fmaf(a[i], bv[j], acc[i][j]);
        }
        __syncthreads();
    }
#pragma unroll
    for(int i=0;i<8;i++){
        float4 o1, o2;
        o1.x=silu(acc[i][0]); o1.y=silu(acc[i][1]); o1.z=silu(acc[i][2]); o1.w=silu(acc[i][3]);
        o2.x=silu(acc[i][4]); o2.y=silu(acc[i][5]); o2.z=silu(acc[i][6]); o2.w=silu(acc[i][7]);
        float* yr = y + (size_t)(b*M + m0 + tr*8 + i)*HW + p0 + tc*8;
        *(float4*)yr     = o1;
        *(float4*)(yr+4) = o2;
    }
}

// ---- head GEMM on tensor cores: wmma m16n16k8 TF32, D[128x64] per CTA ----
__global__ __launch_bounds__(256)
void head_tc_k(const float* __restrict__ x, const float* __restrict__ w,
               float* __restrict__ y){   // M=1280, K=512, P=256
    __shared__ __align__(16) float sm[8704];
    float* As = sm;                // stride 36
    float* Bs = sm + 128*36;       // stride 68
    const int b = blockIdx.z, m0 = blockIdx.y*128, p0 = blockIdx.x*64;
    const int tid = threadIdx.x;
    const int wid = tid>>5;
    const int wm  = wid & 3;
    const int wp  = wid >> 2;
    wmma::fragment<wmma::accumulator,16,16,8,float> c[2][2];
#pragma unroll
    for(int i=0;i<2;i++)
#pragma unroll
    for(int j=0;j<2;j++) wmma::fill_fragment(c[i][j], 0.f);
    const float* xb = x + (size_t)b*512*256;

    for(int kc=0; kc<512; kc+=32){
        for(int i=tid;i<1024;i+=256){
            int m = i>>3, q = (i&7)*4;
            float4 v = *(const float4*)&w[(size_t)(m0+m)*512 + kc + q];
            float* d = &As[m*36+q];
            d[0]=wmma::__float_to_tf32(v.x); d[1]=wmma::__float_to_tf32(v.y);
            d[2]=wmma::__float_to_tf32(v.z); d[3]=wmma::__float_to_tf32(v.w);
        }
        for(int i=tid;i<512;i+=256){
            int kk = i>>4, q = (i&15)*4;
            float4 v = *(const float4*)&xb[(size_t)(kc+kk)*256 + p0 + q];
            float* d = &Bs[kk*68+q];
            d[0]=wmma::__float_to_tf32(v.x); d[1]=wmma::__float_to_tf32(v.y);
            d[2]=wmma::__float_to_tf32(v.z); d[3]=wmma::__float_to_tf32(v.w);
        }
        __syncthreads();
#pragma unroll
        for(int ks=0; ks<4; ks++){
            wmma::fragment<wmma::matrix_a,16,16,8,wmma::precision::tf32,wmma::row_major> a0,a1;
            wmma::fragment<wmma::matrix_b,16,16,8,wmma::precision::tf32,wmma::row_major> b0,b1;
            wmma::load_matrix_sync(a0, &As[(wm*32+ 0)*36 + ks*8], 36);
            wmma::load_matrix_sync(a1, &As[(wm*32+16)*36 + ks*8], 36);
            wmma::load_matrix_sync(b0, &Bs[(ks*8)*68 + wp*32     ], 68);
            wmma::load_matrix_sync(b1, &Bs[(ks*8)*68 + wp*32 + 16], 68);
            wmma::mma_sync(c[0][0], a0, b0, c[0][0]);
            wmma::mma_sync(c[0][1], a0, b1, c[0][1]);
            wmma::mma_sync(c[1][0], a1, b0, c[1][0]);
            wmma::mma_sync(c[1][1], a1, b1, c[1][1]);
        }
        __syncthreads();
    }
    float* Os = sm;
#pragma unroll
    for(int i=0;i<2;i++)
#pragma unroll
    for(int j=0;j<2;j++)
        wmma::store_matrix_sync(&Os[(wm*32+i*16)*68 + wp*32 + j*16], c[i][j], 68, wmma::mem_row_major);
    __syncthreads();
    for(int i=tid;i<2048;i+=256){
        int m = i>>4, q = (i&15)*4;
        float4 v = *(float4*)&Os[m*68+q];
        float4 o;
        o.x=silu(v.x); o.y=silu(v.y); o.z=silu(v.z); o.w=silu(v.w);
        *(float4*)&y[(size_t)(b*1280+m0+m)*256 + p0 + q] = o;
    }
}

// ---------------- small pointwise 1x1 + silu (64x64) ----------------
__global__ void pw_k(const float* __restrict__ x, const float* __restrict__ w,
                     float* __restrict__ y, int M, int K, int HW){
    int b = blockIdx.z, m0 = blockIdx.y*64, p0 = blockIdx.x*64;
    __shared__ float As[16][64];
    __shared__ float Bs[16][64];
    int tid = threadIdx.x;
    int tr = tid>>4, tc = tid&15;
    float acc[4][4] = {};
    const float* xb = x + (size_t)b*K*HW;
    for(int k0=0;k0<K;k0+=16){
#pragma unroll
        for(int r=0;r<4;r++){
            int id = tid + 256*r;
            int m  = id>>4, kk = id&15;
            As[kk][m] = w[(m0+m)*K + k0 + kk];
            int kk2 = id>>6, p = id&63;
            Bs[kk2][p] = xb[(size_t)(k0+kk2)*HW + p0 + p];
        }
        __syncthreads();
#pragma unroll
        for(int kk=0;kk<16;kk++){
            float a0=As[kk][tr*4+0], a1=As[kk][tr*4+1], a2=As[kk][tr*4+2], a3=As[kk][tr*4+3];
            float b0=Bs[kk][tc*4+0], b1=Bs[kk][tc*4+1], b2=Bs[kk][tc*4+2], b3=Bs[kk][tc*4+3];
            acc[0][0]+=a0*b0; acc[0][1]+=a0*b1; acc[0][2]+=a0*b2; acc[0][3]+=a0*b3;
            acc[1][0]+=a1*b0; acc[1][1]+=a1*b1; acc[1][2]+=a1*b2; acc[1][3]+=a1*b3;
            acc[2][0]+=a2*b0; acc[2][1]+=a2*b1; acc[2][2]+=a2*b2; acc[2][3]+=a2*b3;
            acc[3][0]+=a3*b0; acc[3][1]+=a3*b1; acc[3][2]+=a3*b2; acc[3][3]+=a3*b3;
        }
        __syncthreads();
    }
#pragma unroll
    for(int i=0;i<4;i++)
#pragma unroll
    for(int j=0;j<4;j++)
        y[(size_t)(b*M + m0 + tr*4+i)*HW + p0 + tc*4+j] = silu(acc[i][j]);
}

// ---- s partial: chunk computes its weff slice inline, writes partial (no atomics) ----
__global__ void s_part_k(const float* __restrict__ head,
                         const float* __restrict__ proj_w, const float* __restrict__ proj_b,
                         const float* __restrict__ final_w, float* __restrict__ spart){
    const int b = blockIdx.y, chunk = blockIdx.x;
    __shared__ float sw[160];
    const int tid = threadIdx.x;
    if(tid < 160){
        float a = 0.f;
        const float* pc = proj_w + chunk*160 + tid;
#pragma unroll 8
        for(int c=0;c<64;c++) a += final_w[c]*pc[c*1280];
        sw[tid] = a;
    }
    __syncthreads();
    float acc = 0.f;
    if(chunk==0){
        float bsum=0.f;
#pragma unroll 8
        for(int c=0;c<64;c++) bsum += final_w[c]*proj_b[c];
        acc = bsum;
    }
    const float* hb = head + ((size_t)b*1280 + chunk*160)*256 + tid;
#pragma unroll 4
    for(int k=0;k<160;k++) acc += sw[k]*hb[(size_t)k*256];
    spart[(chunk*BN + b)*256 + tid] = acc;
}

// ---------------- out = 0.25*sum_{4x4} clamped-bilinear(sum partials) + final_b ----------------
__global__ void final_k(const float* __restrict__ spart, const float* __restrict__ final_b,
                        float* __restrict__ out){
    int b = blockIdx.x >> 6;
    __shared__ float ss[256];
    int tid = threadIdx.x;
    float v = 0.f;
#pragma unroll
    for(int c=0;c<8;c++) v += spart[(c*BN + b)*256 + tid];
    ss[tid] = v;
    __syncthreads();
    int idx = blockIdx.x*256 + tid;
    int r = idx & 16383; int i = r>>7, j = r&127;
    float acc = 0.f;
#pragma unroll
    for(int dy=0;dy<4;dy++){
        float fy  = (4*i+dy+0.5f)*(1.f/32.f) - 0.5f;
        float y0f = floorf(fy); float f = fy - y0f;
        int y0 = (int)y0f;
        int iy0 = min(max(y0,0),15), iy1 = min(max(y0+1,0),15);
#pragma unroll
        for(int dx=0;dx<4;dx++){
            float fx  = (4*j+dx+0.5f)*(1.f/32.f) - 0.5f;
            float x0f = floorf(fx); float g = fx - x0f;
            int x0 = (int)x0f;
            int ix0 = min(max(x0,0),15), ix1 = min(max(x0+1,0),15);
            float top = ss[iy0*16+ix0]*(1.f-g) + ss[iy0*16+ix1]*g;
            float bot = ss[iy1*16+ix0]*(1.f-g) + ss[iy1*16+ix1]*g;
            acc += top*(1.f-f) + bot*f;
        }
    }
    out[idx] = 0.25f*acc + final_b[0];
}

// ---------------- launch ----------------
extern "C" void kernel_launch(void* const* d_in, const int* in_sizes, int n_in,
                              void* d_out, int out_size){
    const float* img     = (const float*)d_in[0];
    const float* stem_w  = (const float*)d_in[1];
    const float* dw1_w   = (const float*)d_in[2];
    const float* pw1_w   = (const float*)d_in[3];
    const float* dw2_w   = (const float*)d_in[4];
    const float* pw2_w   = (const float*)d_in[5];
    const float* dw3_w   = (const float*)d_in[6];
    const float* pw3_w   = (const float*)d_in[7];
    const float* dw4_w   = (const float*)d_in[8];
    const float* pw4_w   = (const float*)d_in[9];
    const float* head_w  = (const float*)d_in[10];
    const float* proj_w  = (const float*)d_in[11];
    const float* proj_b  = (const float*)d_in[12];
    const float* final_w = (const float*)d_in[13];
    const float* final_b = (const float*)d_in[14];

    float *pA,*pB,*den,*bA,*bB,*spart;
    cudaGetSymbolAddress((void**)&pA,  g_pA);
    cudaGetSymbolAddress((void**)&pB,  g_pB);
    cudaGetSymbolAddress((void**)&den, g_den);
    cudaGetSymbolAddress((void**)&bA,  g_bufA);
    cudaGetSymbolAddress((void**)&bB,  g_bufB);
    cudaGetSymbolAddress((void**)&spart,g_spart);

    cudaFuncSetAttribute(tv5_k<true ,true ,false>, cudaFuncAttributeMaxDynamicSharedMemorySize, TV_SMEM);
    cudaFuncSetAttribute(tv5_k<false,true ,false>, cudaFuncAttributeMaxDynamicSharedMemorySize, TV_SMEM);
    cudaFuncSetAttribute(tv5_k<false,false,true >, cudaFuncAttributeMaxDynamicSharedMemorySize, TV_SMEM);

    dim3 tvg(10,10,BN);
    tv5_k<true ,true ,false><<<tvg,256,TV_SMEM>>>(img, pA, pA, den);  // 1-5   -> pA
    tv5_k<false,true ,false><<<tvg,256,TV_SMEM>>>(img, pA, pB, den);  // 6-10  -> pB
    tv5_k<false,true ,false><<<tvg,256,TV_SMEM>>>(img, pB, pA, den);  // 11-15 -> pA
    tv5_k<false,false,true ><<<tvg,256,TV_SMEM>>>(img, pA, pB, den);  // 16-20 -> den

    stem_k<<<(BN*256*256)/256,256>>>(den, stem_w, bA);                  // [4,32,256,256]
    dw_k<<<(BN*32*128*128)/256,256>>>(bA, dw1_w, bB, 32, 256, 128);     // [4,32,128,128]
    pwb_k<<<dim3(16384/128, 64/64,  BN),128>>>(bB, pw1_w, bA, 64,  32, 16384);
    dw_k<<<(BN*64*64*64)/256,256>>>(bA, dw2_w, bB, 64, 128, 64);
    pwb_k<<<dim3(4096/128, 128/64,  BN),128>>>(bB, pw2_w, bA, 128, 64, 4096);
    dw_k<<<(BN*128*32*32)/256,256>>>(bA, dw3_w, bB, 128, 64, 32);
    pw_k <<<dim3(1024/64, 256/64,   BN),256>>>(bB, pw3_w, bA, 256, 128, 1024);
    dw_k<<<(BN*256*16*16)/256,256>>>(bA, dw4_w, bB, 256, 32, 16);
    pw_k <<<dim3(256/64,  512/64,   BN),256>>>(bB, pw4_w, bA, 512, 256, 256);
    head_tc_k<<<dim3(4, 10, BN),256>>>(bA, head_w, bB);

    s_part_k<<<dim3(8,BN),256>>>(bB, proj_w, proj_b, final_w, spart);
    final_k<<<BN*64,256>>>(spart, final_b, (float*)d_out);
}

// round 14
// speedup vs baseline: 1.4911x; 1.4911x over previous
#include <cuda_runtime.h>
#include <math.h>
#include <mma.h>
using namespace nvcuda;

#define BN 4
#define IH 512
#define IW 512
#define TT 52
#define HALO 6
#define PAD2 32
#define A2 2112
#define TV_SMEM (2*A2*8)

// ---------------- static scratch ----------------
__device__ float g_pA[BN*2*IH*IW];
__device__ float g_pB[BN*2*IH*IW];
__device__ float g_den[BN*IH*IW];
__device__ float g_bufA[8*1024*1024];
__device__ float g_bufB[4*1024*1024];
__device__ float g_spart[8*BN*256];

__device__ __forceinline__ float silu(float x){ return x/(1.f+__expf(-x)); }

// ---- TV Chambolle: 5 fused iterations, float2, x-neighbors via warp shuffle ----
template<bool FIRST, bool INTERIOR, bool WRITE_P, bool WRITE_DEN>
__device__ __forceinline__ void tv_body(
    const float* __restrict__ img, const float* __restrict__ pin,
    float* __restrict__ pout, float* __restrict__ den,
    float2* s0, float2* so)
{
    const int b   = blockIdx.z;
    const int gy0 = blockIdx.y*TT - HALO;
    const int gx0 = blockIdx.x*TT - HALO;
    const int tid = threadIdx.x;
    const int lx2 = tid & 31;          // float2 column == lane
    const int ty0 = tid >> 5;
    const int gxp = gx0 + 2*lx2;
    const float* ib = img + b*(IH*IW);
    const float* q0 = pin + (b*2+0)*(IH*IW);
    const float* q1 = pin + (b*2+1)*(IH*IW);
    const unsigned FM = 0xffffffffu;

    float2 imgv[8], p0v[8], p1v[8];

#pragma unroll
    for(int k=0;k<8;k++){
        const int ly = ty0 + 8*k;
        const int gy = gy0 + ly;
        const int i  = k*256 + tid;
        if(INTERIOR){
            const int g2 = gy*(IW/2) + (gxp>>1);
            imgv[k] = ((const float2*)ib)[g2];
            if(FIRST){ p0v[k]=make_float2(0.f,0.f); p1v[k]=make_float2(0.f,0.f); }
            else { p0v[k]=((const float2*)q0)[g2]; p1v[k]=((const float2*)q1)[g2]; }
        } else {
            const bool iy  = ((unsigned)gy < IH);
            const bool inx = iy && ((unsigned)gxp < IW);
            const bool iny = iy && ((unsigned)(gxp+1) < IW);
            const int gA = gy*IW + gxp, gB = gA+1;
            imgv[k].x = inx ? ib[gA] : 0.f;
            imgv[k].y = iny ? ib[gB] : 0.f;
            if(FIRST){ p0v[k]=make_float2(0.f,0.f); p1v[k]=make_float2(0.f,0.f); }
            else{
                p0v[k].x = inx? q0[gA]:0.f; p0v[k].y = iny? q0[gB]:0.f;
                p1v[k].x = inx? q1[gA]:0.f; p1v[k].y = iny? q1[gB]:0.f;
            }
        }
        s0[i]=p0v[k];
    }
    __syncthreads();

#pragma unroll 1
    for(int it=0; it<5; it++){
        // pass1: out = img + div(p); left-p1 via shuffle, up-p0 via smem
#pragma unroll
        for(int k=0;k<8;k++){
            const int i = k*256 + tid;
            float2 up = s0[i-32];
            float  lf = __shfl_up_sync(FM, p1v[k].y, 1);   // lane0 garbage -> halo
            float2 o;
            o.x = imgv[k].x - p0v[k].x - p1v[k].x + up.x + lf;
            o.y = imgv[k].y - p0v[k].y - p1v[k].y + up.y + p1v[k].x;
            so[i] = o;
        }
        __syncthreads();
        // pass2: p update; right-out via shuffle, down-out via smem
#pragma unroll
        for(int k=0;k<8;k++){
            const int i  = k*256 + tid;
            const int gy = gy0 + ty0 + 8*k;
            float2 o  = so[i];
            float2 dn = so[i+32];
            float  rx = __shfl_down_sync(FM, o.x, 1);      // lane31 garbage -> halo
            float gyx = dn.x - o.x, gyy = dn.y - o.y;
            float gxx = o.y  - o.x, gxy = rx   - o.y;
            if(!INTERIOR){
                if(gy >= IH-1){ gyx=0.f; gyy=0.f; }
                if(gxp+1 >= IW-1) gxy = 0.f;
            }
            float n2x = fmaf(gyx,gyx, gxx*gxx);
            float n2y = fmaf(gyy,gyy, gxy*gxy);
            float nrx, nry, ivx, ivy;
            asm("sqrt.approx.f32 %0, %1;" : "=f"(nrx) : "f"(n2x));
            asm("sqrt.approx.f32 %0, %1;" : "=f"(nry) : "f"(n2y));
            float dx_ = fmaf(2.5f, nrx, 1.0f);
            float dy_ = fmaf(2.5f, nry, 1.0f);
            asm("rcp.approx.f32 %0, %1;" : "=f"(ivx) : "f"(dx_));
            asm("rcp.approx.f32 %0, %1;" : "=f"(ivy) : "f"(dy_));
            float2 np0, np1;
            np0.x = (p0v[k].x - 0.25f*gyx)*ivx;
            np1.x = (p1v[k].x - 0.25f*gxx)*ivx;
            np0.y = (p0v[k].y - 0.25f*gyy)*ivy;
            np1.y = (p1v[k].y - 0.25f*gxy)*ivy;
            if(!INTERIOR){
                const bool iy  = ((unsigned)gy < IH);
                const bool inx = iy && ((unsigned)gxp < IW);
                const bool iny = iy && ((unsigned)(gxp+1) < IW);
                if(!inx){ np0.x=0.f; np1.x=0.f; }
                if(!iny){ np0.y=0.f; np1.y=0.f; }
            }
            p0v[k]=np0; p1v[k]=np1;
            s0[i]=np0;
        }
        __syncthreads();
    }

    const bool wx = (lx2>=3) && (lx2<29) && (gxp < IW);
    if(WRITE_P){
        float2* o0 = (float2*)(pout + (b*2+0)*(IH*IW));
        float2* o1 = (float2*)(pout + (b*2+1)*(IH*IW));
#pragma unroll
        for(int k=0;k<8;k++){
            const int ly = ty0+8*k, gy = gy0+ly;
            if(wx && ly>=HALO && ly<HALO+TT && gy<IH){
                const int g2 = gy*(IW/2) + (gxp>>1);
                o0[g2]=p0v[k]; o1[g2]=p1v[k];
            }
        }
    }
    if(WRITE_DEN){
        float2* db = (float2*)(den + b*(IH*IW));
#pragma unroll
        for(int k=0;k<8;k++){
            const int ly = ty0+8*k, gy = gy0+ly;
            const int i  = k*256+tid;
            float2 up = s0[i-32];
            float  lf = __shfl_up_sync(FM, p1v[k].y, 1);   // warp-uniform
            if(wx && ly>=HALO && ly<HALO+TT && gy<IH){
                float2 d;
                d.x = imgv[k].x - p0v[k].x - p1v[k].x + up.x + lf;
                d.y = imgv[k].y - p0v[k].y - p1v[k].y + up.y + p1v[k].x;
                db[gy*(IW/2) + (gxp>>1)] = d;
            }
        }
    }
}

template<bool FIRST, bool WRITE_P, bool WRITE_DEN>
__global__ __launch_bounds__(256,3)
void tv5_k(const float* __restrict__ img, const float* __restrict__ pin,
           float* __restrict__ pout, float* __restrict__ den){
    extern __shared__ float2 sm2[];
    float2* s0 = sm2 + PAD2;
    float2* so = sm2 + A2 + PAD2;
    const bool interior = (blockIdx.y>=1 && blockIdx.y<=8 &&
                           blockIdx.x>=1 && blockIdx.x<=8);
    if(interior) tv_body<FIRST,true ,WRITE_P,WRITE_DEN>(img,pin,pout,den,s0,so);
    else         tv_body<FIRST,false,WRITE_P,WRITE_DEN>(img,pin,pout,den,s0,so);
}

// ---------------- stem: 1->32ch 3x3 stride2 + silu (fp32) ----------------
__global__ void stem_k(const float* __restrict__ x, const float* __restrict__ w,
                       float* __restrict__ y){
    __shared__ float sw[288];
    for(int i=threadIdx.x;i<288;i+=256) sw[i]=w[i];
    __syncthreads();
    int idx = blockIdx.x*256 + threadIdx.x;
    int b = idx>>16; int r = idx & 65535; int oy=r>>8, ox=r&255;
    const float* xb = x + b*IH*IW;
    float patch[9];
#pragma unroll
    for(int ky=0;ky<3;ky++)
#pragma unroll
    for(int kx=0;kx<3;kx++){
        int iy=2*oy-1+ky, ix=2*ox-1+kx;
        patch[ky*3+kx] = (iy>=0&&iy<IH&&ix>=0&&ix<IW)? xb[iy*IW+ix] : 0.f;
    }
    float* yb = y + (size_t)(b*32)*65536 + oy*256 + ox;
#pragma unroll
    for(int c=0;c<32;c++){
        float acc=0.f;
#pragma unroll
        for(int k=0;k<9;k++) acc += patch[k]*sw[c*9+k];
        yb[c*65536] = silu(acc);
    }
}

// ---------------- depthwise 3x3 stride2 + silu ----------------
__global__ void dw_k(const float* __restrict__ x, const float* __restrict__ w,
                     float* __restrict__ y, int C, int Hi, int Ho){
    int idx = blockIdx.x*256 + threadIdx.x;
    if(idx >= BN*C*Ho*Ho) return;
    int ox = idx % Ho; int t = idx/Ho; int oy=t%Ho; t/=Ho; int c=t%C; int b=t/C;
    const float* xb = x + (size_t)(b*C+c)*Hi*Hi;
    const float* wc = w + c*9;
    float acc=0.f;
#pragma unroll
    for(int ky=0;ky<3;ky++){
        int iy=2*oy-1+ky; if(iy<0||iy>=Hi) continue;
#pragma unroll
        for(int kx=0;kx<3;kx++){
            int ix=2*ox-1+kx; if(ix<0||ix>=Hi) continue;
            acc += xb[iy*Hi+ix]*wc[ky*3+kx];
        }
    }
    y[idx] = silu(acc);
}

// ---------------- big pointwise GEMM: BM=64, BN=128, 128 thr, 8x8 micro ----------------
__global__ __launch_bounds__(128)
void pwb_k(const float* __restrict__ x, const float* __restrict__ w,
           float* __restrict__ y, int M, int K, int HW){
    const int b = blockIdx.z, m0 = blockIdx.y*64, p0 = blockIdx.x*128;
    __shared__ float As[16][68];
    __shared__ float Bs[16][128];
    const int tid = threadIdx.x;
    const int tr = tid>>4, tc = tid&15;
    float acc[8][8] = {};
    const float* xb = x + (size_t)b*K*HW;
    for(int k0=0;k0<K;k0+=16){
#pragma unroll
        for(int r=0;r<2;r++){
            int m = (tid>>2) + 32*r;
            int q = (tid&3)*4;
            float4 v = *(const float4*)&w[(size_t)(m0+m)*K + k0 + q];
            As[q+0][m]=v.x; As[q+1][m]=v.y; As[q+2][m]=v.z; As[q+3][m]=v.w;
        }
#pragma unroll
        for(int r=0;r<4;r++){
            int kk = (tid>>5) + 4*r;
            int p  = (tid&31)*4;
            *(float4*)&Bs[kk][p] = *(const float4*)&xb[(size_t)(k0+kk)*HW + p0 + p];
        }
        __syncthreads();
#pragma unroll
        for(int kk=0;kk<16;kk++){
            float a[8], bv[8];
            *(float4*)&a[0]  = *(float4*)&As[kk][tr*8];
            *(float4*)&a[4]  = *(float4*)&As[kk][tr*8+4];
            *(float4*)&bv[0] = *(float4*)&Bs[kk][tc*8];
            *(float4*)&bv[4] = *(float4*)&Bs[kk][tc*8+4];
#pragma unroll
            for(int i=0;i<8;i++)
#pragma unroll
            for(int j=0;j<8;j++)
                acc[i][j] = fmaf(a[i], bv[j], acc[i][j]);
        }
        __syncthreads();
    }
#pragma unroll
    for(int i=0;i<8;i++){
        float4 o1, o2;
        o1.x=silu(acc[i][0]); o1.y=silu(acc[i][1]); o1.z=silu(acc[i][2]); o1.w=silu(acc[i][3]);
        o2.x=silu(acc[i][4]); o2.y=silu(acc[i][5]); o2.z=silu(acc[i][6]); o2.w=silu(acc[i][7]);
        float* yr = y + (size_t)(b*M + m0 + tr*8 + i)*HW + p0 + tc*8;
        *(float4*)yr     = o1;
        *(float4*)(yr+4) = o2;
    }
}

// ---- head GEMM on tensor cores: wmma m16n16k8 TF32, D[128x64] per CTA ----
__global__ __launch_bounds__(256)
void head_tc_k(const float* __restrict__ x, const float* __restrict__ w,
               float* __restrict__ y){   // M=1280, K=512, P=256
    __shared__ __align__(16) float sm[8704];
    float* As = sm;                // stride 36
    float* Bs = sm + 128*36;       // stride 68
    const int b = blockIdx.z, m0 = blockIdx.y*128, p0 = blockIdx.x*64;
    const int tid = threadIdx.x;
    const int wid = tid>>5;
    const int wm  = wid & 3;
    const int wp  = wid >> 2;
    wmma::fragment<wmma::accumulator,16,16,8,float> c[2][2];
#pragma unroll
    for(int i=0;i<2;i++)
#pragma unroll
    for(int j=0;j<2;j++) wmma::fill_fragment(c[i][j], 0.f);
    const float* xb = x + (size_t)b*512*256;

    for(int kc=0; kc<512; kc+=32){
        for(int i=tid;i<1024;i+=256){
            int m = i>>3, q = (i&7)*4;
            float4 v = *(const float4*)&w[(size_t)(m0+m)*512 + kc + q];
            float* d = &As[m*36+q];
            d[0]=wmma::__float_to_tf32(v.x); d[1]=wmma::__float_to_tf32(v.y);
            d[2]=wmma::__float_to_tf32(v.z); d[3]=wmma::__float_to_tf32(v.w);
        }
        for(int i=tid;i<512;i+=256){
            int kk = i>>4, q = (i&15)*4;
            float4 v = *(const float4*)&xb[(size_t)(kc+kk)*256 + p0 + q];
            float* d = &Bs[kk*68+q];
            d[0]=wmma::__float_to_tf32(v.x); d[1]=wmma::__float_to_tf32(v.y);
            d[2]=wmma::__float_to_tf32(v.z); d[3]=wmma::__float_to_tf32(v.w);
        }
        __syncthreads();
#pragma unroll
        for(int ks=0; ks<4; ks++){
            wmma::fragment<wmma::matrix_a,16,16,8,wmma::precision::tf32,wmma::row_major> a0,a1;
            wmma::fragment<wmma::matrix_b,16,16,8,wmma::precision::tf32,wmma::row_major> b0,b1;
            wmma::load_matrix_sync(a0, &As[(wm*32+ 0)*36 + ks*8], 36);
            wmma::load_matrix_sync(a1, &As[(wm*32+16)*36 + ks*8], 36);
            wmma::load_matrix_sync(b0, &Bs[(ks*8)*68 + wp*32     ], 68);
            wmma::load_matrix_sync(b1, &Bs[(ks*8)*68 + wp*32 + 16], 68);
            wmma::mma_sync(c[0][0], a0, b0, c[0][0]);
            wmma::mma_sync(c[0][1], a0, b1, c[0][1]);
            wmma::mma_sync(c[1][0], a1, b0, c[1][0]);
            wmma::mma_sync(c[1][1], a1, b1, c[1][1]);
        }
        __syncthreads();
    }
    float* Os = sm;
#pragma unroll
    for(int i=0;i<2;i++)
#pragma unroll
    for(int j=0;j<2;j++)
        wmma::store_matrix_sync(&Os[(wm*32+i*16)*68 + wp*32 + j*16], c[i][j], 68, wmma::mem_row_major);
    __syncthreads();
    for(int i=tid;i<2048;i+=256){
        int m = i>>4, q = (i&15)*4;
        float4 v = *(float4*)&Os[m*68+q];
        float4 o;
        o.x=silu(v.x); o.y=silu(v.y); o.z=silu(v.z); o.w=silu(v.w);
        *(float4*)&y[(size_t)(b*1280+m0+m)*256 + p0 + q] = o;
    }
}

// ---------------- small pointwise 1x1 + silu (64x64) ----------------
__global__ void pw_k(const float* __restrict__ x, const float* __restrict__ w,
                     float* __restrict__ y, int M, int K, int HW){
    int b = blockIdx.z, m0 = blockIdx.y*64, p0 = blockIdx.x*64;
    __shared__ float As[16][64];
    __shared__ float Bs[16][64];
    int tid = threadIdx.x;
    int tr = tid>>4, tc = tid&15;
    float acc[4][4] = {};
    const float* xb = x + (size_t)b*K*HW;
    for(int k0=0;k0<K;k0+=16){
#pragma unroll
        for(int r=0;r<4;r++){
            int id = tid + 256*r;
            int m  = id>>4, kk = id&15;
            As[kk][m] = w[(m0+m)*K + k0 + kk];
            int kk2 = id>>6, p = id&63;
            Bs[kk2][p] = xb[(size_t)(k0+kk2)*HW + p0 + p];
        }
        __syncthreads();
#pragma unroll
        for(int kk=0;kk<16;kk++){
            float a0=As[kk][tr*4+0], a1=As[kk][tr*4+1], a2=As[kk][tr*4+2], a3=As[kk][tr*4+3];
            float b0=Bs[kk][tc*4+0], b1=Bs[kk][tc*4+1], b2=Bs[kk][tc*4+2], b3=Bs[kk][tc*4+3];
            acc[0][0]+=a0*b0; acc[0][1]+=a0*b1; acc[0][2]+=a0*b2; acc[0][3]+=a0*b3;
            acc[1][0]+=a1*b0; acc[1][1]+=a1*b1; acc[1][2]+=a1*b2; acc[1][3]+=a1*b3;
            acc[2][0]+=a2*b0; acc[2][1]+=a2*b1; acc[2][2]+=a2*b2; acc[2][3]+=a2*b3;
            acc[3][0]+=a3*b0; acc[3][1]+=a3*b1; acc[3][2]+=a3*b2; acc[3][3]+=a3*b3;
        }
        __syncthreads();
    }
#pragma unroll
    for(int i=0;i<4;i++)
#pragma unroll
    for(int j=0;j<4;j++)
        y[(size_t)(b*M + m0 + tr*4+i)*HW + p0 + tc*4+j] = silu(acc[i][j]);
}

// ---- s partial: chunk computes its weff slice inline, writes partial (no atomics) ----
__global__ void s_part_k(const float* __restrict__ head,
                         const float* __restrict__ proj_w, const float* __restrict__ proj_b,
                         const float* __restrict__ final_w, float* __restrict__ spart){
    const int b = blockIdx.y, chunk = blockIdx.x;
    __shared__ float sw[160];
    const int tid = threadIdx.x;
    if(tid < 160){
        float a = 0.f;
        const float* pc = proj_w + chunk*160 + tid;
#pragma unroll 8
        for(int c=0;c<64;c++) a += final_w[c]*pc[c*1280];
        sw[tid] = a;
    }
    __syncthreads();
    float acc = 0.f;
    if(chunk==0){
        float bsum=0.f;
#pragma unroll 8
        for(int c=0;c<64;c++) bsum += final_w[c]*proj_b[c];
        acc = bsum;
    }
    const float* hb = head + ((size_t)b*1280 + chunk*160)*256 + tid;
#pragma unroll 4
    for(int k=0;k<160;k++) acc += sw[k]*hb[(size_t)k*256];
    spart[(chunk*BN + b)*256 + tid] = acc;
}

// ---------------- out = 0.25*sum_{4x4} clamped-bilinear(sum partials) + final_b ----------------
__global__ void final_k(const float* __restrict__ spart, const float* __restrict__ final_b,
                        float* __restrict__ out){
    int b = blockIdx.x >> 6;
    __shared__ float ss[256];
    int tid = threadIdx.x;
    float v = 0.f;
#pragma unroll
    for(int c=0;c<8;c++) v += spart[(c*BN + b)*256 + tid];
    ss[tid] = v;
    __syncthreads();
    int idx = blockIdx.x*256 + tid;
    int r = idx & 16383; int i = r>>7, j = r&127;
    float acc = 0.f;
#pragma unroll
    for(int dy=0;dy<4;dy++){
        float fy  = (4*i+dy+0.5f)*(1.f/32.f) - 0.5f;
        float y0f = floorf(fy); float f = fy - y0f;
        int y0 = (int)y0f;
        int iy0 = min(max(y0,0),15), iy1 = min(max(y0+1,0),15);
#pragma unroll
        for(int dx=0;dx<4;dx++){
            float fx  = (4*j+dx+0.5f)*(1.f/32.f) - 0.5f;
            float x0f = floorf(fx); float g = fx - x0f;
            int x0 = (int)x0f;
            int ix0 = min(max(x0,0),15), ix1 = min(max(x0+1,0),15);
            float top = ss[iy0*16+ix0]*(1.f-g) + ss[iy0*16+ix1]*g;
            float bot = ss[iy1*16+ix0]*(1.f-g) + ss[iy1*16+ix1]*g;
            acc += top*(1.f-f) + bot*f;
        }
    }
    out[idx] = 0.25f*acc + final_b[0];
}

// ---------------- launch ----------------
extern "C" void kernel_launch(void* const* d_in, const int* in_sizes, int n_in,
                              void* d_out, int out_size){
    const float* img     = (const float*)d_in[0];
    const float* stem_w  = (const float*)d_in[1];
    const float* dw1_w   = (const float*)d_in[2];
    const float* pw1_w   = (const float*)d_in[3];
    const float* dw2_w   = (const float*)d_in[4];
    const float* pw2_w   = (const float*)d_in[5];
    const float* dw3_w   = (const float*)d_in[6];
    const float* pw3_w   = (const float*)d_in[7];
    const float* dw4_w   = (const float*)d_in[8];
    const float* pw4_w   = (const float*)d_in[9];
    const float* head_w  = (const float*)d_in[10];
    const float* proj_w  = (const float*)d_in[11];
    const float* proj_b  = (const float*)d_in[12];
    const float* final_w = (const float*)d_in[13];
    const float* final_b = (const float*)d_in[14];

    float *pA,*pB,*den,*bA,*bB,*spart;
    cudaGetSymbolAddress((void**)&pA,  g_pA);
    cudaGetSymbolAddress((void**)&pB,  g_pB);
    cudaGetSymbolAddress((void**)&den, g_den);
    cudaGetSymbolAddress((void**)&bA,  g_bufA);
    cudaGetSymbolAddress((void**)&bB,  g_bufB);
    cudaGetSymbolAddress((void**)&spart,g_spart);

    cudaFuncSetAttribute(tv5_k<true ,true ,false>, cudaFuncAttributeMaxDynamicSharedMemorySize, TV_SMEM);
    cudaFuncSetAttribute(tv5_k<false,true ,false>, cudaFuncAttributeMaxDynamicSharedMemorySize, TV_SMEM);
    cudaFuncSetAttribute(tv5_k<false,false,true >, cudaFuncAttributeMaxDynamicSharedMemorySize, TV_SMEM);

    dim3 tvg(10,10,BN);
    tv5_k<true ,true ,false><<<tvg,256,TV_SMEM>>>(img, pA, pA, den);  // 1-5   -> pA
    tv5_k<false,true ,false><<<tvg,256,TV_SMEM>>>(img, pA, pB, den);  // 6-10  -> pB
    tv5_k<false,true ,false><<<tvg,256,TV_SMEM>>>(img, pB, pA, den);  // 11-15 -> pA
    tv5_k<false,false,true ><<<tvg,256,TV_SMEM>>>(img, pA, pB, den);  // 16-20 -> den

    stem_k<<<(BN*256*256)/256,256>>>(den, stem_w, bA);                  // [4,32,256,256]
    dw_k<<<(BN*32*128*128)/256,256>>>(bA, dw1_w, bB, 32, 256, 128);     // [4,32,128,128]
    pwb_k<<<dim3(16384/128, 64/64,  BN),128>>>(bB, pw1_w, bA, 64,  32, 16384);
    dw_k<<<(BN*64*64*64)/256,256>>>(bA, dw2_w, bB, 64, 128, 64);
    pwb_k<<<dim3(4096/128, 128/64,  BN),128>>>(bB, pw2_w, bA, 128, 64, 4096);
    dw_k<<<(BN*128*32*32)/256,256>>>(bA, dw3_w, bB, 128, 64, 32);
    pw_k <<<dim3(1024/64, 256/64,   BN),256>>>(bB, pw3_w, bA, 256, 128, 1024);
    dw_k<<<(BN*256*16*16)/256,256>>>(bA, dw4_w, bB, 256, 32, 16);
    pw_k <<<dim3(256/64,  512/64,   BN),256>>>(bB, pw4_w, bA, 512, 256, 256);
    head_tc_k<<<dim3(4, 10, BN),256>>>(bA, head_w, bB);

    s_part_k<<<dim3(8,BN),256>>>(bB, proj_w, proj_b, final_w, spart);
    final_k<<<BN*64,256>>>(spart, final_b, (float*)d_out);
}

// round 15
// speedup vs baseline: 1.5916x; 1.0674x over previous
#include <cuda_runtime.h>
#include <math.h>
#include <mma.h>
using namespace nvcuda;

#define BN 4
#define IH 512
#define IW 512
#define TT 52
#define HALO 6
#define PAD2 32
#define A2 2112
#define TV_SMEM (2*A2*8)

// ---------------- static scratch ----------------
__device__ float g_pA[BN*2*IH*IW];
__device__ float g_pB[BN*2*IH*IW];
__device__ float g_den[BN*IH*IW];
__device__ float g_bufA[8*1024*1024];
__device__ float g_bufB[4*1024*1024];
__device__ float g_spart[10*BN*256];

__device__ __forceinline__ float silu(float x){ return x/(1.f+__expf(-x)); }

// ---- TV Chambolle: 5 fused iterations, float2, x-neighbors via warp shuffle ----
template<bool FIRST, bool INTERIOR, bool WRITE_P, bool WRITE_DEN>
__device__ __forceinline__ void tv_body(
    const float* __restrict__ img, const float* __restrict__ pin,
    float* __restrict__ pout, float* __restrict__ den,
    float2* s0, float2* so)
{
    const int b   = blockIdx.z;
    const int gy0 = blockIdx.y*TT - HALO;
    const int gx0 = blockIdx.x*TT - HALO;
    const int tid = threadIdx.x;
    const int lx2 = tid & 31;
    const int ty0 = tid >> 5;
    const int gxp = gx0 + 2*lx2;
    const float* ib = img + b*(IH*IW);
    const float* q0 = pin + (b*2+0)*(IH*IW);
    const float* q1 = pin + (b*2+1)*(IH*IW);
    const unsigned FM = 0xffffffffu;

    float2 imgv[8], p0v[8], p1v[8];

#pragma unroll
    for(int k=0;k<8;k++){
        const int ly = ty0 + 8*k;
        const int gy = gy0 + ly;
        const int i  = k*256 + tid;
        if(INTERIOR){
            const int g2 = gy*(IW/2) + (gxp>>1);
            imgv[k] = ((const float2*)ib)[g2];
            if(FIRST){ p0v[k]=make_float2(0.f,0.f); p1v[k]=make_float2(0.f,0.f); }
            else { p0v[k]=((const float2*)q0)[g2]; p1v[k]=((const float2*)q1)[g2]; }
        } else {
            const bool iy  = ((unsigned)gy < IH);
            const bool inx = iy && ((unsigned)gxp < IW);
            const bool iny = iy && ((unsigned)(gxp+1) < IW);
            const int gA = gy*IW + gxp, gB = gA+1;
            imgv[k].x = inx ? ib[gA] : 0.f;
            imgv[k].y = iny ? ib[gB] : 0.f;
            if(FIRST){ p0v[k]=make_float2(0.f,0.f); p1v[k]=make_float2(0.f,0.f); }
            else{
                p0v[k].x = inx? q0[gA]:0.f; p0v[k].y = iny? q0[gB]:0.f;
                p1v[k].x = inx? q1[gA]:0.f; p1v[k].y = iny? q1[gB]:0.f;
            }
        }
        s0[i]=p0v[k];
    }
    __syncthreads();

#pragma unroll 1
    for(int it=0; it<5; it++){
#pragma unroll
        for(int k=0;k<8;k++){
            const int i = k*256 + tid;
            float2 up = s0[i-32];
            float  lf = __shfl_up_sync(FM, p1v[k].y, 1);
            float2 o;
            o.x = imgv[k].x - p0v[k].x - p1v[k].x + up.x + lf;
            o.y = imgv[k].y - p0v[k].y - p1v[k].y + up.y + p1v[k].x;
            so[i] = o;
        }
        __syncthreads();
#pragma unroll
        for(int k=0;k<8;k++){
            const int i  = k*256 + tid;
            const int gy = gy0 + ty0 + 8*k;
            float2 o  = so[i];
            float2 dn = so[i+32];
            float  rx = __shfl_down_sync(FM, o.x, 1);
            float gyx = dn.x - o.x, gyy = dn.y - o.y;
            float gxx = o.y  - o.x, gxy = rx   - o.y;
            if(!INTERIOR){
                if(gy >= IH-1){ gyx=0.f; gyy=0.f; }
                if(gxp+1 >= IW-1) gxy = 0.f;
            }
            float n2x = fmaf(gyx,gyx, gxx*gxx);
            float n2y = fmaf(gyy,gyy, gxy*gxy);
            float nrx, nry, ivx, ivy;
            asm("sqrt.approx.f32 %0, %1;" : "=f"(nrx) : "f"(n2x));
            asm("sqrt.approx.f32 %0, %1;" : "=f"(nry) : "f"(n2y));
            float dx_ = fmaf(2.5f, nrx, 1.0f);
            float dy_ = fmaf(2.5f, nry, 1.0f);
            asm("rcp.approx.f32 %0, %1;" : "=f"(ivx) : "f"(dx_));
            asm("rcp.approx.f32 %0, %1;" : "=f"(ivy) : "f"(dy_));
            float2 np0, np1;
            np0.x = (p0v[k].x - 0.25f*gyx)*ivx;
            np1.x = (p1v[k].x - 0.25f*gxx)*ivx;
            np0.y = (p0v[k].y - 0.25f*gyy)*ivy;
            np1.y = (p1v[k].y - 0.25f*gxy)*ivy;
            if(!INTERIOR){
                const bool iy  = ((unsigned)gy < IH);
                const bool inx = iy && ((unsigned)gxp < IW);
                const bool iny = iy && ((unsigned)(gxp+1) < IW);
                if(!inx){ np0.x=0.f; np1.x=0.f; }
                if(!iny){ np0.y=0.f; np1.y=0.f; }
            }
            p0v[k]=np0; p1v[k]=np1;
            s0[i]=np0;
        }
        __syncthreads();
    }

    const bool wx = (lx2>=3) && (lx2<29) && (gxp < IW);
    if(WRITE_P){
        float2* o0 = (float2*)(pout + (b*2+0)*(IH*IW));
        float2* o1 = (float2*)(pout + (b*2+1)*(IH*IW));
#pragma unroll
        for(int k=0;k<8;k++){
            const int ly = ty0+8*k, gy = gy0+ly;
            if(wx && ly>=HALO && ly<HALO+TT && gy<IH){
                const int g2 = gy*(IW/2) + (gxp>>1);
                o0[g2]=p0v[k]; o1[g2]=p1v[k];
            }
        }
    }
    if(WRITE_DEN){
        float2* db = (float2*)(den + b*(IH*IW));
#pragma unroll
        for(int k=0;k<8;k++){
            const int ly = ty0+8*k, gy = gy0+ly;
            const int i  = k*256+tid;
            float2 up = s0[i-32];
            float  lf = __shfl_up_sync(FM, p1v[k].y, 1);
            if(wx && ly>=HALO && ly<HALO+TT && gy<IH){
                float2 d;
                d.x = imgv[k].x - p0v[k].x - p1v[k].x + up.x + lf;
                d.y = imgv[k].y - p0v[k].y - p1v[k].y + up.y + p1v[k].x;
                db[gy*(IW/2) + (gxp>>1)] = d;
            }
        }
    }
}

template<bool FIRST, bool WRITE_P, bool WRITE_DEN>
__global__ __launch_bounds__(256,3)
void tv5_k(const float* __restrict__ img, const float* __restrict__ pin,
           float* __restrict__ pout, float* __restrict__ den){
    extern __shared__ float2 sm2[];
    float2* s0 = sm2 + PAD2;
    float2* so = sm2 + A2 + PAD2;
    const bool interior = (blockIdx.y>=1 && blockIdx.y<=8 &&
                           blockIdx.x>=1 && blockIdx.x<=8);
    if(interior) tv_body<FIRST,true ,WRITE_P,WRITE_DEN>(img,pin,pout,den,s0,so);
    else         tv_body<FIRST,false,WRITE_P,WRITE_DEN>(img,pin,pout,den,s0,so);
}

// ---------------- stem: 1->32ch 3x3 stride2 + silu (fp32) ----------------
__global__ void stem_k(const float* __restrict__ x, const float* __restrict__ w,
                       float* __restrict__ y){
    __shared__ float sw[288];
    for(int i=threadIdx.x;i<288;i+=256) sw[i]=w[i];
    __syncthreads();
    int idx = blockIdx.x*256 + threadIdx.x;
    int b = idx>>16; int r = idx & 65535; int oy=r>>8, ox=r&255;
    const float* xb = x + b*IH*IW;
    float patch[9];
#pragma unroll
    for(int ky=0;ky<3;ky++)
#pragma unroll
    for(int kx=0;kx<3;kx++){
        int iy=2*oy-1+ky, ix=2*ox-1+kx;
        patch[ky*3+kx] = (iy>=0&&iy<IH&&ix>=0&&ix<IW)? xb[iy*IW+ix] : 0.f;
    }
    float* yb = y + (size_t)(b*32)*65536 + oy*256 + ox;
#pragma unroll
    for(int c=0;c<32;c++){
        float acc=0.f;
#pragma unroll
        for(int k=0;k<9;k++) acc += patch[k]*sw[c*9+k];
        yb[c*65536] = silu(acc);
    }
}

// ---------------- depthwise 3x3 stride2 + silu ----------------
__global__ void dw_k(const float* __restrict__ x, const float* __restrict__ w,
                     float* __restrict__ y, int C, int Hi, int Ho){
    int idx = blockIdx.x*256 + threadIdx.x;
    if(idx >= BN*C*Ho*Ho) return;
    int ox = idx % Ho; int t = idx/Ho; int oy=t%Ho; t/=Ho; int c=t%C; int b=t/C;
    const float* xb = x + (size_t)(b*C+c)*Hi*Hi;
    const float* wc = w + c*9;
    float acc=0.f;
#pragma unroll
    for(int ky=0;ky<3;ky++){
        int iy=2*oy-1+ky; if(iy<0||iy>=Hi) continue;
#pragma unroll
        for(int kx=0;kx<3;kx++){
            int ix=2*ox-1+kx; if(ix<0||ix>=Hi) continue;
            acc += xb[iy*Hi+ix]*wc[ky*3+kx];
        }
    }
    y[idx] = silu(acc);
}

// ---------------- big pointwise GEMM: BM=64, BN=128, 128 thr, 8x8 micro ----------------
__global__ __launch_bounds__(128)
void pwb_k(const float* __restrict__ x, const float* __restrict__ w,
           float* __restrict__ y, int M, int K, int HW){
    const int b = blockIdx.z, m0 = blockIdx.y*64, p0 = blockIdx.x*128;
    __shared__ float As[16][68];
    __shared__ float Bs[16][128];
    const int tid = threadIdx.x;
    const int tr = tid>>4, tc = tid&15;
    float acc[8][8] = {};
    const float* xb = x + (size_t)b*K*HW;
    for(int k0=0;k0<K;k0+=16){
#pragma unroll
        for(int r=0;r<2;r++){
            int m = (tid>>2) + 32*r;
            int q = (tid&3)*4;
            float4 v = *(const float4*)&w[(size_t)(m0+m)*K + k0 + q];
            As[q+0][m]=v.x; As[q+1][m]=v.y; As[q+2][m]=v.z; As[q+3][m]=v.w;
        }
#pragma unroll
        for(int r=0;r<4;r++){
            int kk = (tid>>5) + 4*r;
            int p  = (tid&31)*4;
            *(float4*)&Bs[kk][p] = *(const float4*)&xb[(size_t)(k0+kk)*HW + p0 + p];
        }
        __syncthreads();
#pragma unroll
        for(int kk=0;kk<16;kk++){
            float a[8], bv[8];
            *(float4*)&a[0]  = *(float4*)&As[kk][tr*8];
            *(float4*)&a[4]  = *(float4*)&As[kk][tr*8+4];
            *(float4*)&bv[0] = *(float4*)&Bs[kk][tc*8];
            *(float4*)&bv[4] = *(float4*)&Bs[kk][tc*8+4];
#pragma unroll
            for(int i=0;i<8;i++)
#pragma unroll
            for(int j=0;j<8;j++)
                acc[i][j] = fmaf(a[i], bv[j], acc[i][j]);
        }
        __syncthreads();
    }
#pragma unroll
    for(int i=0;i<8;i++){
        float4 o1, o2;
        o1.x=silu(acc[i][0]); o1.y=silu(acc[i][1]); o1.z=silu(acc[i][2]); o1.w=silu(acc[i][3]);
        o2.x=silu(acc[i][4]); o2.y=silu(acc[i][5]); o2.z=silu(acc[i][6]); o2.w=silu(acc[i][7]);
        float* yr = y + (size_t)(b*M + m0 + tr*8 + i)*HW + p0 + tc*8;
        *(float4*)yr     = o1;
        *(float4*)(yr+4) = o2;
    }
}

// ---- head GEMM (TF32 wmma) fused with proj/final reduction: writes s partials ----
__global__ __launch_bounds__(256)
void head_s_k(const float* __restrict__ x, const float* __restrict__ w,
              const float* __restrict__ proj_w, const float* __restrict__ proj_b,
              const float* __restrict__ final_w, float* __restrict__ spart){
    __shared__ __align__(16) float sm[8704];     // As[128][36]+Bs[32][68]; reused as Os[128][68]
    __shared__ float wsl[128];                   // weff slice for this m-chunk
    __shared__ float red[4][68];                 // 4-way pixel reduction
    float* As = sm;
    float* Bs = sm + 128*36;
    const int b = blockIdx.z, mc = blockIdx.y, m0 = mc*128, p0 = blockIdx.x*64;
    const int tid = threadIdx.x;
    const int wid = tid>>5;
    const int wm  = wid & 3;
    const int wp  = wid >> 2;
    wmma::fragment<wmma::accumulator,16,16,8,float> c[2][2];
#pragma unroll
    for(int i=0;i<2;i++)
#pragma unroll
    for(int j=0;j<2;j++) wmma::fill_fragment(c[i][j], 0.f);
    const float* xb = x + (size_t)b*512*256;

    for(int kc=0; kc<512; kc+=32){
        for(int i=tid;i<1024;i+=256){
            int m = i>>3, q = (i&7)*4;
            float4 v = *(const float4*)&w[(size_t)(m0+m)*512 + kc + q];
            float* d = &As[m*36+q];
            d[0]=wmma::__float_to_tf32(v.x); d[1]=wmma::__float_to_tf32(v.y);
            d[2]=wmma::__float_to_tf32(v.z); d[3]=wmma::__float_to_tf32(v.w);
        }
        for(int i=tid;i<512;i+=256){
            int kk = i>>4, q = (i&15)*4;
            float4 v = *(const float4*)&xb[(size_t)(kc+kk)*256 + p0 + q];
            float* d = &Bs[kk*68+q];
            d[0]=wmma::__float_to_tf32(v.x); d[1]=wmma::__float_to_tf32(v.y);
            d[2]=wmma::__float_to_tf32(v.z); d[3]=wmma::__float_to_tf32(v.w);
        }
        __syncthreads();
#pragma unroll
        for(int ks=0; ks<4; ks++){
            wmma::fragment<wmma::matrix_a,16,16,8,wmma::precision::tf32,wmma::row_major> a0,a1;
            wmma::fragment<wmma::matrix_b,16,16,8,wmma::precision::tf32,wmma::row_major> b0,b1;
            wmma::load_matrix_sync(a0, &As[(wm*32+ 0)*36 + ks*8], 36);
            wmma::load_matrix_sync(a1, &As[(wm*32+16)*36 + ks*8], 36);
            wmma::load_matrix_sync(b0, &Bs[(ks*8)*68 + wp*32     ], 68);
            wmma::load_matrix_sync(b1, &Bs[(ks*8)*68 + wp*32 + 16], 68);
            wmma::mma_sync(c[0][0], a0, b0, c[0][0]);
            wmma::mma_sync(c[0][1], a0, b1, c[0][1]);
            wmma::mma_sync(c[1][0], a1, b0, c[1][0]);
            wmma::mma_sync(c[1][1], a1, b1, c[1][1]);
        }
        __syncthreads();
    }
    // park D in smem (pre-silu)
    float* Os = sm;
#pragma unroll
    for(int i=0;i<2;i++)
#pragma unroll
    for(int j=0;j<2;j++)
        wmma::store_matrix_sync(&Os[(wm*32+i*16)*68 + wp*32 + j*16], c[i][j], 68, wmma::mem_row_major);
    // weff slice for m0..m0+127
    if(tid < 128){
        float a = 0.f;
        const float* pc = proj_w + m0 + tid;
#pragma unroll 8
        for(int cc=0;cc<64;cc++) a += final_w[cc]*pc[cc*1280];
        wsl[tid] = a;
    }
    __syncthreads();
    // partial s: 4 thread-groups of 64 pixels, each sums 32 m's
    {
        const int p = tid & 63, g = tid >> 6;
        float acc = 0.f;
#pragma unroll 8
        for(int m=g*32; m<g*32+32; m++)
            acc += wsl[m]*silu(Os[m*68 + p]);
        red[g][p] = acc;
    }
    __syncthreads();
    if(tid < 64){
        float v = red[0][tid] + red[1][tid] + red[2][tid] + red[3][tid];
        if(mc == 0){
            float bsum = 0.f;
#pragma unroll 8
            for(int cc=0;cc<64;cc++) bsum += final_w[cc]*proj_b[cc];
            v += bsum;
        }
        spart[(mc*BN + b)*256 + p0 + tid] = v;
    }
}

// ---------------- small pointwise 1x1 + silu (64x64) ----------------
__global__ void pw_k(const float* __restrict__ x, const float* __restrict__ w,
                     float* __restrict__ y, int M, int K, int HW){
    int b = blockIdx.z, m0 = blockIdx.y*64, p0 = blockIdx.x*64;
    __shared__ float As[16][64];
    __shared__ float Bs[16][64];
    int tid = threadIdx.x;
    int tr = tid>>4, tc = tid&15;
    float acc[4][4] = {};
    const float* xb = x + (size_t)b*K*HW;
    for(int k0=0;k0<K;k0+=16){
#pragma unroll
        for(int r=0;r<4;r++){
            int id = tid + 256*r;
            int m  = id>>4, kk = id&15;
            As[kk][m] = w[(m0+m)*K + k0 + kk];
            int kk2 = id>>6, p = id&63;
            Bs[kk2][p] = xb[(size_t)(k0+kk2)*HW + p0 + p];
        }
        __syncthreads();
#pragma unroll
        for(int kk=0;kk<16;kk++){
            float a0=As[kk][tr*4+0], a1=As[kk][tr*4+1], a2=As[kk][tr*4+2], a3=As[kk][tr*4+3];
            float b0=Bs[kk][tc*4+0], b1=Bs[kk][tc*4+1], b2=Bs[kk][tc*4+2], b3=Bs[kk][tc*4+3];
            acc[0][0]+=a0*b0; acc[0][1]+=a0*b1; acc[0][2]+=a0*b2; acc[0][3]+=a0*b3;
            acc[1][0]+=a1*b0; acc[1][1]+=a1*b1; acc[1][2]+=a1*b2; acc[1][3]+=a1*b3;
            acc[2][0]+=a2*b0; acc[2][1]+=a2*b1; acc[2][2]+=a2*b2; acc[2][3]+=a2*b3;
            acc[3][0]+=a3*b0; acc[3][1]+=a3*b1; acc[3][2]+=a3*b2; acc[3][3]+=a3*b3;
        }
        __syncthreads();
    }
#pragma unroll
    for(int i=0;i<4;i++)
#pragma unroll
    for(int j=0;j<4;j++)
        y[(size_t)(b*M + m0 + tr*4+i)*HW + p0 + tc*4+j] = silu(acc[i][j]);
}

// ---------------- out = 0.25*sum_{4x4} clamped-bilinear(sum 10 partials) + final_b ----------------
__global__ void final_k(const float* __restrict__ spart, const float* __restrict__ final_b,
                        float* __restrict__ out){
    int b = blockIdx.x >> 6;
    __shared__ float ss[256];
    int tid = threadIdx.x;
    float v = 0.f;
#pragma unroll
    for(int c=0;c<10;c++) v += spart[(c*BN + b)*256 + tid];
    ss[tid] = v;
    __syncthreads();
    int idx = blockIdx.x*256 + tid;
    int r = idx & 16383; int i = r>>7, j = r&127;
    float acc = 0.f;
#pragma unroll
    for(int dy=0;dy<4;dy++){
        float fy  = (4*i+dy+0.5f)*(1.f/32.f) - 0.5f;
        float y0f = floorf(fy); float f = fy - y0f;
        int y0 = (int)y0f;
        int iy0 = min(max(y0,0),15), iy1 = min(max(y0+1,0),15);
#pragma unroll
        for(int dx=0;dx<4;dx++){
            float fx  = (4*j+dx+0.5f)*(1.f/32.f) - 0.5f;
            float x0f = floorf(fx); float g = fx - x0f;
            int x0 = (int)x0f;
            int ix0 = min(max(x0,0),15), ix1 = min(max(x0+1,0),15);
            float top = ss[iy0*16+ix0]*(1.f-g) + ss[iy0*16+ix1]*g;
            float bot = ss[iy1*16+ix0]*(1.f-g) + ss[iy1*16+ix1]*g;
            acc += top*(1.f-f) + bot*f;
        }
    }
    out[idx] = 0.25f*acc + final_b[0];
}

// ---------------- launch ----------------
extern "C" void kernel_launch(void* const* d_in, const int* in_sizes, int n_in,
                              void* d_out, int out_size){
    const float* img     = (const float*)d_in[0];
    const float* stem_w  = (const float*)d_in[1];
    const float* dw1_w   = (const float*)d_in[2];
    const float* pw1_w   = (const float*)d_in[3];
    const float* dw2_w   = (const float*)d_in[4];
    const float* pw2_w   = (const float*)d_in[5];
    const float* dw3_w   = (const float*)d_in[6];
    const float* pw3_w   = (const float*)d_in[7];
    const float* dw4_w   = (const float*)d_in[8];
    const float* pw4_w   = (const float*)d_in[9];
    const float* head_w  = (const float*)d_in[10];
    const float* proj_w  = (const float*)d_in[11];
    const float* proj_b  = (const float*)d_in[12];
    const float* final_w = (const float*)d_in[13];
    const float* final_b = (const float*)d_in[14];

    float *pA,*pB,*den,*bA,*bB,*spart;
    cudaGetSymbolAddress((void**)&pA,  g_pA);
    cudaGetSymbolAddress((void**)&pB,  g_pB);
    cudaGetSymbolAddress((void**)&den, g_den);
    cudaGetSymbolAddress((void**)&bA,  g_bufA);
    cudaGetSymbolAddress((void**)&bB,  g_bufB);
    cudaGetSymbolAddress((void**)&spart,g_spart);

    cudaFuncSetAttribute(tv5_k<true ,true ,false>, cudaFuncAttributeMaxDynamicSharedMemorySize, TV_SMEM);
    cudaFuncSetAttribute(tv5_k<false,true ,false>, cudaFuncAttributeMaxDynamicSharedMemorySize, TV_SMEM);
    cudaFuncSetAttribute(tv5_k<false,false,true >, cudaFuncAttributeMaxDynamicSharedMemorySize, TV_SMEM);

    dim3 tvg(10,10,BN);
    tv5_k<true ,true ,false><<<tvg,256,TV_SMEM>>>(img, pA, pA, den);  // 1-5   -> pA
    tv5_k<false,true ,false><<<tvg,256,TV_SMEM>>>(img, pA, pB, den);  // 6-10  -> pB
    tv5_k<false,true ,false><<<tvg,256,TV_SMEM>>>(img, pB, pA, den);  // 11-15 -> pA
    tv5_k<false,false,true ><<<tvg,256,TV_SMEM>>>(img, pA, pB, den);  // 16-20 -> den

    stem_k<<<(BN*256*256)/256,256>>>(den, stem_w, bA);                  // [4,32,256,256]
    dw_k<<<(BN*32*128*128)/256,256>>>(bA, dw1_w, bB, 32, 256, 128);     // [4,32,128,128]
    pwb_k<<<dim3(16384/128, 64/64,  BN),128>>>(bB, pw1_w, bA, 64,  32, 16384);
    dw_k<<<(BN*64*64*64)/256,256>>>(bA, dw2_w, bB, 64, 128, 64);
    pwb_k<<<dim3(4096/128, 128/64,  BN),128>>>(bB, pw2_w, bA, 128, 64, 4096);
    dw_k<<<(BN*128*32*32)/256,256>>>(bA, dw3_w, bB, 128, 64, 32);
    pw_k <<<dim3(1024/64, 256/64,   BN),256>>>(bB, pw3_w, bA, 256, 128, 1024);
    dw_k<<<(BN*256*16*16)/256,256>>>(bA, dw4_w, bB, 256, 32, 16);
    pw_k <<<dim3(256/64,  512/64,   BN),256>>>(bB, pw4_w, bA, 512, 256, 256);
    // fused head (TF32 tensor cores) + proj/final reduction -> s partials
    head_s_k<<<dim3(4, 10, BN),256>>>(bA, head_w, proj_w, proj_b, final_w, spart);

    final_k<<<BN*64,256>>>(spart, final_b, (float*)d_out);
}